// round 15
// baseline (speedup 1.0000x reference)
#include <cuda_runtime.h>
#include <cuda_fp16.h>
#include <cstdint>
#include <cstring>

// ---------------- constants ----------------
#define ZT      128          // z rows per CTA
#define NTH     512          // 16 warps: 4 row-groups x 4 col-groups (32x16 tiles)
#define NCHUNK  33           // circulant-difference chunks d=0..32
#define NPREP   128          // blocks that participate in prep (< 148 residents!)
#define NTILES  1024         // Z / ZT

#define FH_STRIDE 208        // bytes per fp16 f row (104 halves, 96 used)

// smem layout (bytes)
#define RING_H   24576                        // per-half 3 x 8KB B ring
#define OFF_F0   49152                        // fp16 f tile (row-doubled)
#define OFF_F1   75776                        // fp16 f tile shifted by one col
#define SMEM_TOTAL 118784                     // padded to 116KB -> forces 1 CTA/SM

// scratch
__device__ float g_M[262144];                                // fp32 M[k,i,j], 1MB
__device__ __align__(1024) unsigned char g_B[NCHUNK * 8192]; // pre-swizzled fp16 chunks
__device__ int g_mdone;                                      // prep phase-1 counter
__device__ int g_bdone;                                      // prep phase-2 counter

// ---------------- helpers ----------------
__device__ __forceinline__ uint32_t smem_u32(const void* p) {
    uint32_t a;
    asm("{ .reg .u64 t; cvta.to.shared.u64 t, %1; cvt.u32.u64 %0, t; }"
        : "=r"(a) : "l"(p));
    return a;
}

__device__ __forceinline__ uint32_t h2u(float lo, float hi) {
    __half2 h = __floats2half2_rn(lo, hi);
    uint32_t u;
    memcpy(&u, &h, 4);
    return u;
}

__device__ __forceinline__ uint32_t mulh2(uint32_t a, uint32_t b) {
    uint32_t d;
    asm("mul.rn.f16x2 %0, %1, %2;" : "=r"(d) : "r"(a), "r"(b));
    return d;
}

__device__ __forceinline__ void cpa16(uint32_t s, const void* g) {
    asm volatile("cp.async.cg.shared.global [%0], [%1], 16;" :: "r"(s), "l"(g) : "memory");
}

__device__ __forceinline__ void ldsm4t(uint32_t* r, uint32_t addr) {
    asm volatile(
        "ldmatrix.sync.aligned.m8n8.x4.trans.shared.b16 {%0,%1,%2,%3}, [%4];"
        : "=r"(r[0]), "=r"(r[1]), "=r"(r[2]), "=r"(r[3]) : "r"(addr));
}

__device__ __forceinline__ void mma16816(float* d,
                                         uint32_t a0, uint32_t a1, uint32_t a2, uint32_t a3,
                                         uint32_t b0, uint32_t b1) {
    asm volatile(
        "mma.sync.aligned.m16n8k16.row.col.f32.f16.f16.f32 "
        "{%0,%1,%2,%3}, {%4,%5,%6,%7}, {%8,%9}, {%0,%1,%2,%3};"
        : "+f"(d[0]), "+f"(d[1]), "+f"(d[2]), "+f"(d[3])
        : "r"(a0), "r"(a1), "r"(a2), "r"(a3), "r"(b0), "r"(b1));
}

__device__ __forceinline__ void half_bar(int id) {
    asm volatile("bar.sync %0, 256;" :: "r"(id) : "memory");
}

// ---------------- fused main kernel ----------------
extern "C" __global__ void __launch_bounds__(NTH, 1)
lts_main(const float* __restrict__ f, const float* __restrict__ mix,
         const float* __restrict__ wgt, float* __restrict__ out) {
    extern __shared__ __align__(1024) unsigned char smem[];
    const uint32_t sb = smem_u32(smem);

    const int tid  = threadIdx.x;
    const int wid  = tid >> 5;
    const int lane = tid & 31;
    const int z0   = blockIdx.x * ZT;

    const int rg   = wid & 3;                 // row group: rows rg*32 .. rg*32+31
    const int cg   = wid >> 2;                // col group: cols cg*16 .. cg*16+15
    const int half = wid >> 3;                // barrier/ring half (cg 0-1 vs 2-3)
    const int htid = tid & 255;               // thread index within half
    const int g    = lane >> 2;               // row within group 0..7
    const int c    = lane & 3;                // col pair 0..3

    const uint32_t ringbase = sb + (uint32_t)half * RING_H;

    // ================= inline prep (blocks 0..NPREP-1) =================
    if (blockIdx.x < NPREP) {
        // phase 1: M slice — this block computes floats [bid*2048, bid*2048+2048)
        {
            float* ws = (float*)(smem + OFF_F0);   // reuse F area pre-fill
            if (tid < 32) ws[tid] = wgt[tid];
            __syncthreads();

            size_t base = ((size_t)blockIdx.x * NTH + tid) * 4;
            float4 s = make_float4(0.f, 0.f, 0.f, 0.f);
#pragma unroll 16
            for (int w = 0; w < 32; ++w) {
                float4 m = __ldg((const float4*)(mix + (size_t)w * 262144 + base));
                float cw = ws[w];
                s.x += cw * m.x; s.y += cw * m.y; s.z += cw * m.z; s.w += cw * m.w;
            }
            *(float4*)(g_M + base) = s;
            __threadfence();
            __syncthreads();
            if (tid == 0) atomicAdd(&g_mdone, 1);
        }

        // wait all M slices
        if (tid == 0) {
            while (*(volatile int*)&g_mdone < NPREP) __nanosleep(64);
        }
        __syncthreads();
        __threadfence();

        // phase 2: fold share — 1056 halves per block (128*1056 = 33*4096)
        {
            const int fbase = blockIdx.x * 1056;
#pragma unroll
            for (int q = 0; q < 3; ++q) {
                int fi = fbase + q * NTH + tid;
                if (fi < fbase + 1056) {
                    int d   = fi >> 12;
                    int rem = fi & 4095;
                    int cc  = rem >> 6;
                    int k   = rem & 63;
                    int j2  = (cc + d) & 63;

                    float v = g_M[k * 4096 + cc * 64 + j2];
                    if (d > 0) v += g_M[k * 4096 + j2 * 64 + cc];
                    if (d == 32) v *= 0.5f;

                    unsigned short h;
                    {
                        __half hh = __float2half_rn(v);
                        memcpy(&h, &hh, 2);
                    }
                    uint32_t off = (uint32_t)cc * 128 + (uint32_t)k * 2;
                    off ^= ((uint32_t)(cc & 7)) << 4;       // SW128-style swizzle
                    *(unsigned short*)(g_B + (size_t)d * 8192 + off) = h;
                }
            }
            __threadfence();
            __syncthreads();
            if (tid == 0) atomicAdd(&g_bdone, 1);
        }
        __syncthreads();   // everyone past ws reuse before F fill below
    }

    // ================= F-tile prologue (all blocks, full CTA) =================
    {
        const float4* src = (const float4*)(f + (size_t)z0 * 64);
#pragma unroll
        for (int q = 0; q < (ZT * 16) / NTH; ++q) {
            int idx = tid + q * NTH;            // float4 index
            int row = idx >> 4;
            int c4  = idx & 15;
            float4 v = src[idx];
            uint32_t w0 = h2u(v.x, v.y), w1 = h2u(v.z, v.w);
            uint32_t* p = (uint32_t*)(smem + OFF_F0 + row * FH_STRIDE + c4 * 8);
            p[0] = w0; p[1] = w1;
            if (c4 < 8) {
                uint32_t* pd = (uint32_t*)(smem + OFF_F0 + row * FH_STRIDE + 128 + c4 * 8);
                pd[0] = w0; pd[1] = w1;
            }
        }
#pragma unroll
        for (int q = 0; q < (ZT * 4) / NTH; ++q) {
            int idx = tid + q * NTH;
            int row = idx >> 2;
            int w   = idx & 3;
            *(uint32_t*)(smem + OFF_F0 + row * FH_STRIDE + 192 + w * 4) = 0;
        }
    }
    __syncthreads();

    // ---- build F1 (shifted by one half) via funnel shift of F0 words
    {
#pragma unroll
        for (int q = 0; q < (ZT * 48) / NTH; ++q) {
            int idx = tid + q * NTH;
            int row = idx / 48;
            int w   = idx - row * 48;
            const uint32_t* pr = (const uint32_t*)(smem + OFF_F0 + row * FH_STRIDE + w * 4);
            uint32_t a = pr[0], b = pr[1];
            *(uint32_t*)(smem + OFF_F1 + row * FH_STRIDE + w * 4) =
                __funnelshift_r(a, b, 16);
        }
    }

    // fixed factors: half2 at cols (16s+2c, +1) [a] and (+8,+9) [b], 4 rows (2m x 2h)
    uint32_t fja[2][2][4], fjb[2][2][4];
#pragma unroll
    for (int m = 0; m < 2; ++m)
#pragma unroll
        for (int h = 0; h < 2; ++h) {
            int row = rg * 32 + m * 16 + h * 8 + g;
            const unsigned char* bp = smem + OFF_F0 + row * FH_STRIDE + c * 4;
#pragma unroll
            for (int s = 0; s < 4; ++s) {
                fja[m][h][s] = *(const uint32_t*)(bp + s * 32);
                fjb[m][h][s] = *(const uint32_t*)(bp + s * 32 + 16);
            }
        }
    __syncthreads();   // F1 visible to all

    // ================= gate on g_B ready, then start B stream =================
    if (tid == 0) {
        while (*(volatile int*)&g_bdone < NPREP) __nanosleep(64);
    }
    __syncthreads();
    __threadfence();

    // ---- prefetch B stages 0,1 into this half's ring (one commit group each)
#pragma unroll
    for (int s = 0; s < 2; ++s) {
        uint32_t dst = ringbase + s * 8192 + htid * 32;
        const unsigned char* src = g_B + (size_t)s * 8192 + htid * 32;
        cpa16(dst, src); cpa16(dst + 16, src + 16);
        asm volatile("cp.async.commit_group;" ::: "memory");
    }

    // ldmatrix address components (buffer-local)
    const uint32_t row_base = (lane & 7) + 8 * ((lane >> 3) & 1);
    const uint32_t n0_base  = 8 * (lane >> 4);
    const uint32_t raw      = row_base * 128 + n0_base * 2;
    const uint32_t xconst   = (row_base & 7) << 4;
    const uint32_t colbyte  = (uint32_t)cg * 32;   // 16 cols per cg

    float acc[2][2][4];
#pragma unroll
    for (int m = 0; m < 2; ++m)
#pragma unroll
        for (int p = 0; p < 2; ++p)
#pragma unroll
            for (int e = 0; e < 4; ++e) acc[m][p][e] = 0.f;

    const int barid = 1 + half;

    // ---- main chunk loop d = 0..32, per-half 3-stage ring, per-half barrier
#pragma unroll 1
    for (int d = 0; d < NCHUNK; ++d) {
        const uint32_t bbuf = ringbase + (uint32_t)(d % 3) * 8192;

        asm volatile("cp.async.wait_group 1;" ::: "memory");
        half_bar(barid);

        if (d + 2 < NCHUNK) {
            uint32_t dst = ringbase + (uint32_t)((d + 2) % 3) * 8192 + htid * 32;
            const unsigned char* src = g_B + (size_t)(d + 2) * 8192 + htid * 32;
            cpa16(dst, src); cpa16(dst + 16, src + 16);
        }
        asm volatile("cp.async.commit_group;" ::: "memory");

        const int off_tile = (d & 1) ? (OFF_F1 + (d - 1) * 2) : (OFF_F0 + d * 2);
        const unsigned char* u0base = smem + off_tile + (rg * 32 + g) * FH_STRIDE + c * 4;

        // per k-step: 1 ldsm.x4 (16 cols), af production for 2 m-tiles, 4 MMAs
#pragma unroll
        for (int s = 0; s < 4; ++s) {
            uint32_t br[4];
            {
                uint32_t off = (raw + (uint32_t)s * 2048 + colbyte) ^ xconst;
                ldsm4t(br, bbuf + off);
            }

            uint32_t af[2][4];
#pragma unroll
            for (int m = 0; m < 2; ++m) {
                const unsigned char* u0 = u0base + m * (16 * FH_STRIDE) + s * 32;
                const unsigned char* u1 = u0 + 8 * FH_STRIDE;
                af[m][0] = mulh2(fja[m][0][s], *(const uint32_t*)(u0));
                af[m][1] = mulh2(fja[m][1][s], *(const uint32_t*)(u1));
                af[m][2] = mulh2(fjb[m][0][s], *(const uint32_t*)(u0 + 16));
                af[m][3] = mulh2(fjb[m][1][s], *(const uint32_t*)(u1 + 16));
            }

#pragma unroll
            for (int m = 0; m < 2; ++m) {
                mma16816(acc[m][0], af[m][0], af[m][1], af[m][2], af[m][3], br[0], br[1]);
                mma16816(acc[m][1], af[m][0], af[m][1], af[m][2], af[m][3], br[2], br[3]);
            }
        }
    }

    // ---- epilogue: rows rg*32 + m*16 + {g, g+8}, cols cg*16 + p*8 + 2c
#pragma unroll
    for (int m = 0; m < 2; ++m) {
        float* o0 = out + (size_t)(z0 + rg * 32 + m * 16 + g) * 64;
        float* o1 = o0 + 8 * 64;
#pragma unroll
        for (int p = 0; p < 2; ++p) {
            int n = cg * 16 + p * 8 + 2 * c;
            *(float2*)(o0 + n) = make_float2(acc[m][p][0], acc[m][p][1]);
            *(float2*)(o1 + n) = make_float2(acc[m][p][2], acc[m][p][3]);
        }
    }
}

// ---------------- launch ----------------
extern "C" void kernel_launch(void* const* d_in, const int* in_sizes, int n_in,
                              void* d_out, int out_size) {
    (void)n_in; (void)out_size;
    const float* f   = (const float*)d_in[0];   // [Z, 64] fp32
    const float* mix = (const float*)d_in[1];   // [32, 64, 64, 64] fp32
    const float* wgt = (const float*)d_in[2];   // [32] fp32
    float* out = (float*)d_out;                 // [Z, 64] fp32

    cudaFuncSetAttribute(lts_main, cudaFuncAttributeMaxDynamicSharedMemorySize,
                         SMEM_TOTAL);

    // reset prep flags each launch (graph-legal memset nodes; no allocation)
    void *pm = nullptr, *pb = nullptr;
    cudaGetSymbolAddress(&pm, g_mdone);
    cudaGetSymbolAddress(&pb, g_bdone);
    cudaMemsetAsync(pm, 0, sizeof(int));
    cudaMemsetAsync(pb, 0, sizeof(int));

    lts_main<<<NTILES, NTH, SMEM_TOTAL>>>(f, mix, wgt, out);
}

// round 16
// speedup vs baseline: 1.4113x; 1.4113x over previous
#include <cuda_runtime.h>
#include <cuda_fp16.h>
#include <cstdint>
#include <cstring>

// ---------------- constants ----------------
#define ZT      128          // z rows per tile
#define NTH     256          // 8 warps: 4 row-groups x 2 col-groups (32x32 tiles)
#define NCHUNK  33           // circulant-difference chunks d=0..32
#define NPREP   256          // blocks that participate in prep
#define NTILES  1024         // Z / ZT
#define NPERS   296          // persistent CTAs (2 per SM x 148)

#define FH_STRIDE 208        // bytes per fp16 f row (104 halves, 96 used)

// smem layout (bytes)
#define OFF_B    0                            // 3 x 8KB B ring
#define OFF_F0   24576                        // fp16 f tile (row-doubled)
#define OFF_F1   (24576 + ZT * FH_STRIDE)     // fp16 f tile shifted by one col
#define SMEM_TOTAL (OFF_F1 + ZT * FH_STRIDE)  // 77824

// scratch
__device__ float g_M[262144];                                // fp32 M[k,i,j], 1MB
__device__ __align__(1024) unsigned char g_B[NCHUNK * 8192]; // pre-swizzled fp16 chunks
__device__ int g_mdone;                                      // prep phase-1 counter
__device__ int g_bdone;                                      // prep phase-2 counter
__device__ unsigned int g_tile;                              // dynamic tile counter

// ---------------- helpers ----------------
__device__ __forceinline__ uint32_t smem_u32(const void* p) {
    uint32_t a;
    asm("{ .reg .u64 t; cvta.to.shared.u64 t, %1; cvt.u32.u64 %0, t; }"
        : "=r"(a) : "l"(p));
    return a;
}

__device__ __forceinline__ uint32_t h2u(float lo, float hi) {
    __half2 h = __floats2half2_rn(lo, hi);
    uint32_t u;
    memcpy(&u, &h, 4);
    return u;
}

__device__ __forceinline__ uint32_t mulh2(uint32_t a, uint32_t b) {
    uint32_t d;
    asm("mul.rn.f16x2 %0, %1, %2;" : "=r"(d) : "r"(a), "r"(b));
    return d;
}

__device__ __forceinline__ void cpa16(uint32_t s, const void* g) {
    asm volatile("cp.async.cg.shared.global [%0], [%1], 16;" :: "r"(s), "l"(g) : "memory");
}

__device__ __forceinline__ void ldsm4t(uint32_t* r, uint32_t addr) {
    asm volatile(
        "ldmatrix.sync.aligned.m8n8.x4.trans.shared.b16 {%0,%1,%2,%3}, [%4];"
        : "=r"(r[0]), "=r"(r[1]), "=r"(r[2]), "=r"(r[3]) : "r"(addr));
}

__device__ __forceinline__ void mma16816(float* d,
                                         uint32_t a0, uint32_t a1, uint32_t a2, uint32_t a3,
                                         uint32_t b0, uint32_t b1) {
    asm volatile(
        "mma.sync.aligned.m16n8k16.row.col.f32.f16.f16.f32 "
        "{%0,%1,%2,%3}, {%4,%5,%6,%7}, {%8,%9}, {%0,%1,%2,%3};"
        : "+f"(d[0]), "+f"(d[1]), "+f"(d[2]), "+f"(d[3])
        : "r"(a0), "r"(a1), "r"(a2), "r"(a3), "r"(b0), "r"(b1));
}

// ---------------- fused persistent kernel ----------------
extern "C" __global__ void __launch_bounds__(NTH, 2)
lts_main(const float* __restrict__ f, const float* __restrict__ mix,
         const float* __restrict__ wgt, float* __restrict__ out) {
    extern __shared__ __align__(1024) unsigned char smem[];
    const uint32_t sb = smem_u32(smem);

    const int tid  = threadIdx.x;
    const int wid  = tid >> 5;
    const int lane = tid & 31;

    const int rg = wid & 3;                   // row group: rows rg*32 .. rg*32+31
    const int cg = wid >> 2;                  // col group: cols cg*32 .. cg*32+31
    const int g  = lane >> 2;                 // row within group 0..7
    const int c  = lane & 3;                  // col pair 0..3

    // ================= inline prep (blocks 0..NPREP-1) =================
    if (blockIdx.x < NPREP) {
        // phase 1: M slice — this block computes floats [bid*1024, bid*1024+1024)
        {
            float* ws = (float*)(smem + OFF_F0);   // reuse F area pre-fill
            if (tid < 32) ws[tid] = wgt[tid];
            __syncthreads();

            size_t base = ((size_t)blockIdx.x * NTH + tid) * 4;
            float4 s = make_float4(0.f, 0.f, 0.f, 0.f);
#pragma unroll 16
            for (int w = 0; w < 32; ++w) {
                float4 m = __ldg((const float4*)(mix + (size_t)w * 262144 + base));
                float cw = ws[w];
                s.x += cw * m.x; s.y += cw * m.y; s.z += cw * m.z; s.w += cw * m.w;
            }
            *(float4*)(g_M + base) = s;
            __threadfence();
            __syncthreads();
            if (tid == 0) atomicAdd(&g_mdone, 1);
        }

        // wait all M slices
        if (tid == 0) {
            while (*(volatile int*)&g_mdone < NPREP) __nanosleep(64);
        }
        __syncthreads();
        __threadfence();

        // phase 2: fold share — 528 halves per block (256*528 = 33*4096)
        {
            const int fbase = blockIdx.x * 528;
#pragma unroll
            for (int q = 0; q < 3; ++q) {
                int fi = fbase + q * NTH + tid;
                if (fi < fbase + 528) {
                    int d   = fi >> 12;
                    int rem = fi & 4095;
                    int cc  = rem >> 6;
                    int k   = rem & 63;
                    int j2  = (cc + d) & 63;

                    float v = g_M[k * 4096 + cc * 64 + j2];
                    if (d > 0) v += g_M[k * 4096 + j2 * 64 + cc];
                    if (d == 32) v *= 0.5f;

                    unsigned short h;
                    {
                        __half hh = __float2half_rn(v);
                        memcpy(&h, &hh, 2);
                    }
                    uint32_t off = (uint32_t)cc * 128 + (uint32_t)k * 2;
                    off ^= ((uint32_t)(cc & 7)) << 4;       // SW128-style swizzle
                    *(unsigned short*)(g_B + (size_t)d * 8192 + off) = h;
                }
            }
            __threadfence();
            __syncthreads();
            if (tid == 0) atomicAdd(&g_bdone, 1);
        }
        __syncthreads();
    }

    // ================= gate on g_B ready (once per CTA) =================
    if (tid == 0) {
        while (*(volatile int*)&g_bdone < NPREP) __nanosleep(64);
    }
    __syncthreads();
    __threadfence();

    // ldmatrix address components (buffer-local)
    const uint32_t row_base = (lane & 7) + 8 * ((lane >> 3) & 1);
    const uint32_t n0_base  = 8 * (lane >> 4);
    const uint32_t raw      = row_base * 128 + n0_base * 2;
    const uint32_t xconst   = (row_base & 7) << 4;

    __shared__ unsigned int s_tile;

    // ================= persistent tile loop (dynamic stealing) =================
    for (;;) {
        // previous tile's in-flight cp.async and smem readers must be done
        asm volatile("cp.async.wait_group 0;" ::: "memory");
        if (tid == 0) s_tile = atomicAdd(&g_tile, 1u);
        __syncthreads();
        const unsigned int tile = s_tile;
        if (tile >= NTILES) break;
        const int z0 = (int)tile * ZT;

        // ---- prefetch B stages 0,1 (one commit group each)
#pragma unroll
        for (int s = 0; s < 2; ++s) {
            uint32_t dst = sb + OFF_B + s * 8192 + tid * 32;
            const unsigned char* src = g_B + (size_t)s * 8192 + tid * 32;
            cpa16(dst, src); cpa16(dst + 16, src + 16);
            asm volatile("cp.async.commit_group;" ::: "memory");
        }

        // ---- fill F0: fp16 f tile [ZT x 96] (cols 64..95 duplicate 0..31), pad zero
        {
            const float4* src = (const float4*)(f + (size_t)z0 * 64);
#pragma unroll
            for (int q = 0; q < (ZT * 16) / NTH; ++q) {
                int idx = tid + q * NTH;            // float4 index
                int row = idx >> 4;
                int c4  = idx & 15;
                float4 v = src[idx];
                uint32_t w0 = h2u(v.x, v.y), w1 = h2u(v.z, v.w);
                uint32_t* p = (uint32_t*)(smem + OFF_F0 + row * FH_STRIDE + c4 * 8);
                p[0] = w0; p[1] = w1;
                if (c4 < 8) {
                    uint32_t* pd = (uint32_t*)(smem + OFF_F0 + row * FH_STRIDE + 128 + c4 * 8);
                    pd[0] = w0; pd[1] = w1;
                }
            }
#pragma unroll
            for (int q = 0; q < (ZT * 4) / NTH; ++q) {
                int idx = tid + q * NTH;
                int row = idx >> 2;
                int w   = idx & 3;
                *(uint32_t*)(smem + OFF_F0 + row * FH_STRIDE + 192 + w * 4) = 0;
            }
        }
        __syncthreads();

        // ---- build F1 (shifted by one half) via funnel shift of F0 words
        {
#pragma unroll
            for (int q = 0; q < (ZT * 48) / NTH; ++q) {
                int idx = tid + q * NTH;
                int row = idx / 48;
                int w   = idx - row * 48;
                const uint32_t* pr = (const uint32_t*)(smem + OFF_F0 + row * FH_STRIDE + w * 4);
                uint32_t a = pr[0], b = pr[1];
                *(uint32_t*)(smem + OFF_F1 + row * FH_STRIDE + w * 4) =
                    __funnelshift_r(a, b, 16);
            }
        }

        // fixed factors: half2 at cols (16s+2c, +1) [a] and (+8,+9) [b], 4 rows
        uint32_t fja[2][2][4], fjb[2][2][4];
#pragma unroll
        for (int m = 0; m < 2; ++m)
#pragma unroll
            for (int h = 0; h < 2; ++h) {
                int row = rg * 32 + m * 16 + h * 8 + g;
                const unsigned char* bp = smem + OFF_F0 + row * FH_STRIDE + c * 4;
#pragma unroll
                for (int s = 0; s < 4; ++s) {
                    fja[m][h][s] = *(const uint32_t*)(bp + s * 32);
                    fjb[m][h][s] = *(const uint32_t*)(bp + s * 32 + 16);
                }
            }
        __syncthreads();   // F1 visible

        float acc[2][4][4];
#pragma unroll
        for (int m = 0; m < 2; ++m)
#pragma unroll
            for (int p = 0; p < 4; ++p)
#pragma unroll
                for (int e = 0; e < 4; ++e) acc[m][p][e] = 0.f;

        // ---- chunk loop d = 0..32, 3-stage B ring, one chunk of fetch slack
#pragma unroll 1
        for (int d = 0; d < NCHUNK; ++d) {
            const uint32_t bbuf = sb + OFF_B + (uint32_t)(d % 3) * 8192;

            asm volatile("cp.async.wait_group 1;" ::: "memory");
            __syncthreads();

            if (d + 2 < NCHUNK) {
                uint32_t dst = sb + OFF_B + (uint32_t)((d + 2) % 3) * 8192 + tid * 32;
                const unsigned char* src = g_B + (size_t)(d + 2) * 8192 + tid * 32;
                cpa16(dst, src); cpa16(dst + 16, src + 16);
            }
            asm volatile("cp.async.commit_group;" ::: "memory");

            const int off_tile = (d & 1) ? (OFF_F1 + (d - 1) * 2) : (OFF_F0 + d * 2);
            const unsigned char* u0base = smem + off_tile + (rg * 32 + g) * FH_STRIDE + c * 4;

            // per k-step: produce A fragments (8 LDS + 8 HMUL2), 2 ldmatrix, 8 MMA
#pragma unroll
            for (int s = 0; s < 4; ++s) {
                uint32_t af[2][4];
#pragma unroll
                for (int m = 0; m < 2; ++m) {
                    const unsigned char* u0 = u0base + m * (16 * FH_STRIDE) + s * 32;
                    const unsigned char* u1 = u0 + 8 * FH_STRIDE;
                    af[m][0] = mulh2(fja[m][0][s], *(const uint32_t*)(u0));
                    af[m][1] = mulh2(fja[m][1][s], *(const uint32_t*)(u1));
                    af[m][2] = mulh2(fjb[m][0][s], *(const uint32_t*)(u0 + 16));
                    af[m][3] = mulh2(fjb[m][1][s], *(const uint32_t*)(u1 + 16));
                }
#pragma unroll
                for (int p2 = 0; p2 < 2; ++p2) {
                    uint32_t br[4];
                    uint32_t off = (raw + (uint32_t)s * 2048 +
                                    (uint32_t)(cg * 2 + p2) * 32) ^ xconst;
                    ldsm4t(br, bbuf + off);
#pragma unroll
                    for (int m = 0; m < 2; ++m) {
                        mma16816(acc[m][2 * p2 + 0], af[m][0], af[m][1],
                                 af[m][2], af[m][3], br[0], br[1]);
                        mma16816(acc[m][2 * p2 + 1], af[m][0], af[m][1],
                                 af[m][2], af[m][3], br[2], br[3]);
                    }
                }
            }
        }

        // ---- epilogue: rows rg*32 + m*16 + {g, g+8}, cols cg*32 + p*8 + 2c
#pragma unroll
        for (int m = 0; m < 2; ++m) {
            float* o0 = out + (size_t)(z0 + rg * 32 + m * 16 + g) * 64;
            float* o1 = o0 + 8 * 64;
#pragma unroll
            for (int p = 0; p < 4; ++p) {
                int n = cg * 32 + p * 8 + 2 * c;
                *(float2*)(o0 + n) = make_float2(acc[m][p][0], acc[m][p][1]);
                *(float2*)(o1 + n) = make_float2(acc[m][p][2], acc[m][p][3]);
            }
        }
        __syncthreads();   // all readers of F/acc done before next tile overwrites
    }
}

// ---------------- launch ----------------
extern "C" void kernel_launch(void* const* d_in, const int* in_sizes, int n_in,
                              void* d_out, int out_size) {
    (void)n_in; (void)out_size;
    const float* f   = (const float*)d_in[0];   // [Z, 64] fp32
    const float* mix = (const float*)d_in[1];   // [32, 64, 64, 64] fp32
    const float* wgt = (const float*)d_in[2];   // [32] fp32
    float* out = (float*)d_out;                 // [Z, 64] fp32

    cudaFuncSetAttribute(lts_main, cudaFuncAttributeMaxDynamicSharedMemorySize,
                         SMEM_TOTAL);

    // reset prep flags + tile counter each launch (graph-legal memset nodes)
    void *pm = nullptr, *pb = nullptr, *pt = nullptr;
    cudaGetSymbolAddress(&pm, g_mdone);
    cudaGetSymbolAddress(&pb, g_bdone);
    cudaGetSymbolAddress(&pt, g_tile);
    cudaMemsetAsync(pm, 0, sizeof(int));
    cudaMemsetAsync(pb, 0, sizeof(int));
    cudaMemsetAsync(pt, 0, sizeof(unsigned int));

    lts_main<<<NPERS, NTH, SMEM_TOTAL>>>(f, mix, wgt, out);
}

// round 17
// speedup vs baseline: 1.5182x; 1.0758x over previous
#include <cuda_runtime.h>
#include <cuda_fp16.h>
#include <cstdint>
#include <cstring>

// ---------------- constants ----------------
#define ZT      128          // z rows per CTA
#define NTH     256          // 8 warps: 4 row-groups x 2 col-groups (32x32 tiles)
#define NCHUNK  33           // circulant-difference chunks d=0..32
#define NPREP   256          // blocks that participate in prep
#define NTILES  1024         // Z / ZT

#define FH_STRIDE 208        // bytes per fp16 f row (104 halves, 96 used)

// smem layout (bytes)
#define OFF_B    0                            // 3 x 8KB B ring
#define OFF_F0   24576                        // fp16 f tile (row-doubled)
#define OFF_F1   (24576 + ZT * FH_STRIDE)     // fp16 f tile shifted by one col
#define OFF_MBAR (OFF_F1 + ZT * FH_STRIDE)    // 6 mbarriers: full[3], empty[3]
#define SMEM_TOTAL (OFF_MBAR + 64)            // 77888

// scratch
__device__ float g_M[262144];                                // fp32 M[k,i,j], 1MB
__device__ __align__(1024) unsigned char g_B[NCHUNK * 8192]; // pre-swizzled fp16 chunks
__device__ int g_mdone;                                      // prep phase-1 counter
__device__ int g_bdone;                                      // prep phase-2 counter

// ---------------- helpers ----------------
__device__ __forceinline__ uint32_t smem_u32(const void* p) {
    uint32_t a;
    asm("{ .reg .u64 t; cvta.to.shared.u64 t, %1; cvt.u32.u64 %0, t; }"
        : "=r"(a) : "l"(p));
    return a;
}

__device__ __forceinline__ uint32_t h2u(float lo, float hi) {
    __half2 h = __floats2half2_rn(lo, hi);
    uint32_t u;
    memcpy(&u, &h, 4);
    return u;
}

__device__ __forceinline__ uint32_t mulh2(uint32_t a, uint32_t b) {
    uint32_t d;
    asm("mul.rn.f16x2 %0, %1, %2;" : "=r"(d) : "r"(a), "r"(b));
    return d;
}

__device__ __forceinline__ void ldsm4t(uint32_t* r, uint32_t addr) {
    asm volatile(
        "ldmatrix.sync.aligned.m8n8.x4.trans.shared.b16 {%0,%1,%2,%3}, [%4];"
        : "=r"(r[0]), "=r"(r[1]), "=r"(r[2]), "=r"(r[3]) : "r"(addr));
}

__device__ __forceinline__ void mma16816(float* d,
                                         uint32_t a0, uint32_t a1, uint32_t a2, uint32_t a3,
                                         uint32_t b0, uint32_t b1) {
    asm volatile(
        "mma.sync.aligned.m16n8k16.row.col.f32.f16.f16.f32 "
        "{%0,%1,%2,%3}, {%4,%5,%6,%7}, {%8,%9}, {%0,%1,%2,%3};"
        : "+f"(d[0]), "+f"(d[1]), "+f"(d[2]), "+f"(d[3])
        : "r"(a0), "r"(a1), "r"(a2), "r"(a3), "r"(b0), "r"(b1));
}

__device__ __forceinline__ void mbar_init(uint32_t mb, uint32_t cnt) {
    asm volatile("mbarrier.init.shared.b64 [%0], %1;" :: "r"(mb), "r"(cnt) : "memory");
}

__device__ __forceinline__ void mbar_expect_tx(uint32_t mb, uint32_t bytes) {
    asm volatile("mbarrier.arrive.expect_tx.shared.b64 _, [%0], %1;"
                 :: "r"(mb), "r"(bytes) : "memory");
}

__device__ __forceinline__ void mbar_arrive(uint32_t mb) {
    asm volatile("mbarrier.arrive.shared.b64 _, [%0];" :: "r"(mb) : "memory");
}

__device__ __forceinline__ void mbar_wait(uint32_t mb, uint32_t parity) {
    asm volatile(
        "{\n\t.reg .pred P;\n\t"
        "LW_%=:\n\t"
        "mbarrier.try_wait.parity.acquire.cta.shared::cta.b64 P, [%0], %1, 0x989680;\n\t"
        "@P bra.uni LD_%=;\n\t"
        "bra.uni LW_%=;\n\t"
        "LD_%=:\n\t}"
        :: "r"(mb), "r"(parity) : "memory");
}

__device__ __forceinline__ void bulk_cp(uint32_t dst, const void* src,
                                        uint32_t bytes, uint32_t mb) {
    asm volatile(
        "cp.async.bulk.shared::cta.global.mbarrier::complete_tx::bytes [%0], [%1], %2, [%3];"
        :: "r"(dst), "l"(src), "r"(bytes), "r"(mb) : "memory");
}

// ---------------- fused main kernel ----------------
extern "C" __global__ void __launch_bounds__(NTH, 2)
lts_main(const float* __restrict__ f, const float* __restrict__ mix,
         const float* __restrict__ wgt, float* __restrict__ out) {
    extern __shared__ __align__(1024) unsigned char smem[];
    const uint32_t sb = smem_u32(smem);

    const int tid  = threadIdx.x;
    const int wid  = tid >> 5;
    const int lane = tid & 31;
    const int z0   = blockIdx.x * ZT;

    const int rg = wid & 3;                   // row group: rows rg*32 .. rg*32+31
    const int cg = wid >> 2;                  // col group: cols cg*32 .. cg*32+31
    const int g  = lane >> 2;                 // row within group 0..7
    const int c  = lane & 3;                  // col pair 0..3

    const uint32_t MB_FULL  = sb + OFF_MBAR;        // full[s]  at +s*8
    const uint32_t MB_EMPTY = sb + OFF_MBAR + 24;   // empty[s] at +s*8

    // ================= inline prep (blocks 0..NPREP-1) =================
    if (blockIdx.x < NPREP) {
        // phase 1: M slice — this block computes floats [bid*1024, bid*1024+1024)
        {
            float* ws = (float*)(smem + OFF_F0);   // reuse F area pre-fill
            if (tid < 32) ws[tid] = wgt[tid];
            __syncthreads();

            size_t base = ((size_t)blockIdx.x * NTH + tid) * 4;
            float4 s = make_float4(0.f, 0.f, 0.f, 0.f);
#pragma unroll 16
            for (int w = 0; w < 32; ++w) {
                float4 m = __ldg((const float4*)(mix + (size_t)w * 262144 + base));
                float cw = ws[w];
                s.x += cw * m.x; s.y += cw * m.y; s.z += cw * m.z; s.w += cw * m.w;
            }
            *(float4*)(g_M + base) = s;
            __threadfence();
            __syncthreads();
            if (tid == 0) atomicAdd(&g_mdone, 1);
        }

        // wait all M slices
        if (tid == 0) {
            while (*(volatile int*)&g_mdone < NPREP) __nanosleep(64);
        }
        __syncthreads();
        __threadfence();

        // phase 2: fold share — 528 halves per block (256*528 = 33*4096)
        {
            const int fbase = blockIdx.x * 528;
#pragma unroll
            for (int q = 0; q < 3; ++q) {
                int fi = fbase + q * NTH + tid;
                if (fi < fbase + 528) {
                    int d   = fi >> 12;
                    int rem = fi & 4095;
                    int cc  = rem >> 6;
                    int k   = rem & 63;
                    int j2  = (cc + d) & 63;

                    float v = g_M[k * 4096 + cc * 64 + j2];
                    if (d > 0) v += g_M[k * 4096 + j2 * 64 + cc];
                    if (d == 32) v *= 0.5f;

                    unsigned short h;
                    {
                        __half hh = __float2half_rn(v);
                        memcpy(&h, &hh, 2);
                    }
                    uint32_t off = (uint32_t)cc * 128 + (uint32_t)k * 2;
                    off ^= ((uint32_t)(cc & 7)) << 4;       // SW128-style swizzle
                    *(unsigned short*)(g_B + (size_t)d * 8192 + off) = h;
                }
            }
            __threadfence();
            __syncthreads();
            if (tid == 0) atomicAdd(&g_bdone, 1);
        }
        __syncthreads();   // everyone past ws reuse before F fill below
    }

    // ================= F-tile prologue (all blocks) =================
    if (tid == 0) {
#pragma unroll
        for (int s = 0; s < 3; ++s) {
            mbar_init(MB_FULL + s * 8, 1);     // completed by bulk-copy tx
            mbar_init(MB_EMPTY + s * 8, 8);    // one arrive per warp
        }
    }
    {
        const float4* src = (const float4*)(f + (size_t)z0 * 64);
#pragma unroll
        for (int q = 0; q < (ZT * 16) / NTH; ++q) {
            int idx = tid + q * NTH;            // float4 index
            int row = idx >> 4;
            int c4  = idx & 15;
            float4 v = src[idx];
            uint32_t w0 = h2u(v.x, v.y), w1 = h2u(v.z, v.w);
            uint32_t* p = (uint32_t*)(smem + OFF_F0 + row * FH_STRIDE + c4 * 8);
            p[0] = w0; p[1] = w1;
            if (c4 < 8) {
                uint32_t* pd = (uint32_t*)(smem + OFF_F0 + row * FH_STRIDE + 128 + c4 * 8);
                pd[0] = w0; pd[1] = w1;
            }
        }
#pragma unroll
        for (int q = 0; q < (ZT * 4) / NTH; ++q) {
            int idx = tid + q * NTH;
            int row = idx >> 2;
            int w   = idx & 3;
            *(uint32_t*)(smem + OFF_F0 + row * FH_STRIDE + 192 + w * 4) = 0;
        }
    }
    __syncthreads();

    // ---- build F1 (shifted by one half) via funnel shift of F0 words
    {
#pragma unroll
        for (int q = 0; q < (ZT * 48) / NTH; ++q) {
            int idx = tid + q * NTH;
            int row = idx / 48;
            int w   = idx - row * 48;
            const uint32_t* pr = (const uint32_t*)(smem + OFF_F0 + row * FH_STRIDE + w * 4);
            uint32_t a = pr[0], b = pr[1];
            *(uint32_t*)(smem + OFF_F1 + row * FH_STRIDE + w * 4) =
                __funnelshift_r(a, b, 16);
        }
    }

    // fixed factors: half2 at cols (16s+2c, +1) [a] and (+8,+9) [b], 4 rows (2m x 2h)
    uint32_t fja[2][2][4], fjb[2][2][4];
#pragma unroll
    for (int m = 0; m < 2; ++m)
#pragma unroll
        for (int h = 0; h < 2; ++h) {
            int row = rg * 32 + m * 16 + h * 8 + g;
            const unsigned char* bp = smem + OFF_F0 + row * FH_STRIDE + c * 4;
#pragma unroll
            for (int s = 0; s < 4; ++s) {
                fja[m][h][s] = *(const uint32_t*)(bp + s * 32);
                fjb[m][h][s] = *(const uint32_t*)(bp + s * 32 + 16);
            }
        }
    __syncthreads();   // F1 + mbarrier init visible

    // ================= gate on g_B ready, then start producer =================
    if (tid == 0) {
        while (*(volatile int*)&g_bdone < NPREP) __nanosleep(64);
    }
    __syncthreads();
    __threadfence();

    // preload all 3 ring slots (thread 0 = async producer)
    if (tid == 0) {
#pragma unroll
        for (int s = 0; s < 3; ++s) {
            mbar_expect_tx(MB_FULL + s * 8, 8192);
            bulk_cp(sb + OFF_B + s * 8192, g_B + (size_t)s * 8192, 8192, MB_FULL + s * 8);
        }
    }

    // ldmatrix address components (buffer-local)
    const uint32_t row_base = (lane & 7) + 8 * ((lane >> 3) & 1);
    const uint32_t n0_base  = 8 * (lane >> 4);
    const uint32_t raw      = row_base * 128 + n0_base * 2;
    const uint32_t xconst   = (row_base & 7) << 4;

    float acc[2][4][4];
#pragma unroll
    for (int m = 0; m < 2; ++m)
#pragma unroll
        for (int p = 0; p < 4; ++p)
#pragma unroll
            for (int e = 0; e < 4; ++e) acc[m][p][e] = 0.f;

    // ---- main chunk loop d = 0..32; mbarrier pipeline, no CTA barriers
    int s3 = 0;        // slot = d % 3
    int par = 0;       // parity = (d / 3) & 1
#pragma unroll 1
    for (int d = 0; d < NCHUNK; ++d) {
        const uint32_t fullmb  = MB_FULL + s3 * 8;
        const uint32_t emptymb = MB_EMPTY + s3 * 8;
        const uint32_t bbuf    = sb + OFF_B + (uint32_t)s3 * 8192;

        // wait chunk d's data (warp-local; warps may skew)
        mbar_wait(fullmb, (uint32_t)par);

        const int off_tile = (d & 1) ? (OFF_F1 + (d - 1) * 2) : (OFF_F0 + d * 2);
        const unsigned char* u0base = smem + off_tile + (rg * 32 + g) * FH_STRIDE + c * 4;

        // per k-step: produce A fragments (8 LDS + 8 HMUL2), 2 ldmatrix, 8 MMA
#pragma unroll
        for (int s = 0; s < 4; ++s) {
            uint32_t af[2][4];
#pragma unroll
            for (int m = 0; m < 2; ++m) {
                const unsigned char* u0 = u0base + m * (16 * FH_STRIDE) + s * 32;
                const unsigned char* u1 = u0 + 8 * FH_STRIDE;
                af[m][0] = mulh2(fja[m][0][s], *(const uint32_t*)(u0));
                af[m][1] = mulh2(fja[m][1][s], *(const uint32_t*)(u1));
                af[m][2] = mulh2(fjb[m][0][s], *(const uint32_t*)(u0 + 16));
                af[m][3] = mulh2(fjb[m][1][s], *(const uint32_t*)(u1 + 16));
            }
#pragma unroll
            for (int p2 = 0; p2 < 2; ++p2) {
                uint32_t br[4];
                uint32_t off = (raw + (uint32_t)s * 2048 +
                                (uint32_t)(cg * 2 + p2) * 32) ^ xconst;
                ldsm4t(br, bbuf + off);
#pragma unroll
                for (int m = 0; m < 2; ++m) {
                    mma16816(acc[m][2 * p2 + 0], af[m][0], af[m][1],
                             af[m][2], af[m][3], br[0], br[1]);
                    mma16816(acc[m][2 * p2 + 1], af[m][0], af[m][1],
                             af[m][2], af[m][3], br[2], br[3]);
                }
            }
        }

        // this warp is done with slot s3 for chunk d
        if (lane == 0) mbar_arrive(emptymb);

        // producer: refill slot s3 with chunk d+3 once all 8 warps released it
        if (tid == 0 && d + 3 < NCHUNK) {
            mbar_wait(emptymb, (uint32_t)par);
            mbar_expect_tx(fullmb, 8192);
            bulk_cp(bbuf, g_B + (size_t)(d + 3) * 8192, 8192, fullmb);
        }

        if (++s3 == 3) { s3 = 0; par ^= 1; }
    }

    // ---- epilogue: rows rg*32 + m*16 + {g, g+8}, cols cg*32 + p*8 + 2c
#pragma unroll
    for (int m = 0; m < 2; ++m) {
        float* o0 = out + (size_t)(z0 + rg * 32 + m * 16 + g) * 64;
        float* o1 = o0 + 8 * 64;
#pragma unroll
        for (int p = 0; p < 4; ++p) {
            int n = cg * 32 + p * 8 + 2 * c;
            *(float2*)(o0 + n) = make_float2(acc[m][p][0], acc[m][p][1]);
            *(float2*)(o1 + n) = make_float2(acc[m][p][2], acc[m][p][3]);
        }
    }
}

// ---------------- launch ----------------
extern "C" void kernel_launch(void* const* d_in, const int* in_sizes, int n_in,
                              void* d_out, int out_size) {
    (void)n_in; (void)out_size;
    const float* f   = (const float*)d_in[0];   // [Z, 64] fp32
    const float* mix = (const float*)d_in[1];   // [32, 64, 64, 64] fp32
    const float* wgt = (const float*)d_in[2];   // [32] fp32
    float* out = (float*)d_out;                 // [Z, 64] fp32

    cudaFuncSetAttribute(lts_main, cudaFuncAttributeMaxDynamicSharedMemorySize,
                         SMEM_TOTAL);

    // reset prep flags each launch (graph-legal memset nodes; no allocation)
    void *pm = nullptr, *pb = nullptr;
    cudaGetSymbolAddress(&pm, g_mdone);
    cudaGetSymbolAddress(&pb, g_bdone);
    cudaMemsetAsync(pm, 0, sizeof(int));
    cudaMemsetAsync(pb, 0, sizeof(int));

    lts_main<<<NTILES, NTH, SMEM_TOTAL>>>(f, mix, wgt, out);
}